// round 16
// baseline (speedup 1.0000x reference)
#include <cuda_runtime.h>
#include <cuda_fp16.h>

// Problem dims
#define U_LEN 2048
#define R_LEN 256
#define L_LEN 1024
#define M_LEN 512
#define D_DIM 1024
#define NHEAD 16
#define HDIM  64
#define QLEN  (U_LEN + R_LEN)                   // 2304
#define KVLEN (M_LEN + R_LEN + L_LEN + U_LEN)   // 3840
#define MR    (M_LEN + R_LEN)                   // 768
#define KVIN  (MR + U_LEN)                      // 2816

// GEMM tiles: 128 rows x 16 halves = 1024 words (4KB), XOR swizzle w^(r&7)
#define GT_W 1024
#define GT_B 4096
#define NKT  64

// Attention K / V^T: rows of 64 halves = 32 words + 4 pad = stride 36 words
#define KV_STR   36
#define KTILE_W  (64 * KV_STR)       // 2304 words = 9216 B
#define KHEAD_W  (KVLEN * KV_STR)    // 138240 words
#define NVTILES  (KVLEN / 64)        // 60

// log2(e) folded into q scaling
#define QSCALE (0.125f * 1.4426950408889634f)

// Scratch (no cudaMalloc allowed)
__device__ __align__(16) unsigned g_kvin_h [22 * 64 * GT_W];
__device__ __align__(16) unsigned g_attn_h [18 * 64 * GT_W];
__device__ __align__(16) unsigned g_Wq_h   [ 8 * 64 * GT_W];
__device__ __align__(16) unsigned g_Wkv_h  [16 * 64 * GT_W];
__device__ __align__(16) unsigned g_Wo_h   [ 8 * 64 * GT_W];
__device__ __align__(16) unsigned g_query_h[QLEN * 512];          // fp16 row-major
__device__ __align__(16) unsigned g_key_h  [NHEAD * KHEAD_W];     // [head][row][36w]
__device__ __align__(16) __half   g_val_h  [NHEAD * NVTILES * 64 * 72]; // [head][tile][d][72h]

// ---------------------------------------------------------------------------
// helpers
// ---------------------------------------------------------------------------
__device__ __forceinline__ unsigned f22h2(float a, float b) {
    __half2 h = __floats2half2_rn(a, b);
    return *reinterpret_cast<unsigned*>(&h);
}
__device__ __forceinline__ float2 h22f2(unsigned u) {
    return __half22float2(*reinterpret_cast<__half2*>(&u));
}

__device__ __forceinline__ unsigned ex2h2(unsigned p) {
    unsigned r;
    asm("ex2.approx.f16x2 %0, %1;" : "=r"(r) : "r"(p));
    return r;
}
__device__ __forceinline__ unsigned hsub2(unsigned a, unsigned b) {
    unsigned r;
    asm("sub.f16x2 %0, %1, %2;" : "=r"(r) : "r"(a), "r"(b));
    return r;
}
__device__ __forceinline__ unsigned hmax2(unsigned a, unsigned b) {
    unsigned r;
    asm("max.f16x2 %0, %1, %2;" : "=r"(r) : "r"(a), "r"(b));
    return r;
}
__device__ __forceinline__ unsigned hadd2u(unsigned a, unsigned b) {
    unsigned r;
    asm("add.f16x2 %0, %1, %2;" : "=r"(r) : "r"(a), "r"(b));
    return r;
}

// fp32-accumulate fp16 MMA (GEMMs)
__device__ __forceinline__ void mma_f16(float* d, const unsigned* a, unsigned b0, unsigned b1) {
    asm volatile(
        "mma.sync.aligned.m16n8k16.row.col.f32.f16.f16.f32 "
        "{%0,%1,%2,%3}, {%4,%5,%6,%7}, {%8,%9}, {%0,%1,%2,%3};"
        : "+f"(d[0]), "+f"(d[1]), "+f"(d[2]), "+f"(d[3])
        : "r"(a[0]), "r"(a[1]), "r"(a[2]), "r"(a[3]), "r"(b0), "r"(b1));
}

// fp16-accumulate fp16 MMA (attention, 2x rate)
__device__ __forceinline__ void mma_f16h(unsigned* d, const unsigned* a, unsigned b0, unsigned b1) {
    asm volatile(
        "mma.sync.aligned.m16n8k16.row.col.f16.f16.f16.f16 "
        "{%0,%1}, {%2,%3,%4,%5}, {%6,%7}, {%0,%1};"
        : "+r"(d[0]), "+r"(d[1])
        : "r"(a[0]), "r"(a[1]), "r"(a[2]), "r"(a[3]), "r"(b0), "r"(b1));
}

__device__ __forceinline__ unsigned smaddr(const void* p) {
    return (unsigned)__cvta_generic_to_shared(p);
}
__device__ __forceinline__ void mbar_init(unsigned a) {
    asm volatile("mbarrier.init.shared.b64 [%0], 1;" :: "r"(a) : "memory");
}
__device__ __forceinline__ void mbar_expect(unsigned a, unsigned tx) {
    asm volatile("mbarrier.arrive.expect_tx.shared.b64 _, [%0], %1;" :: "r"(a), "r"(tx) : "memory");
}
__device__ __forceinline__ void bulk_g2s(unsigned sdst, const void* gsrc, unsigned bytes, unsigned mbar) {
    asm volatile("cp.async.bulk.shared::cta.global.mbarrier::complete_tx::bytes [%0], [%1], %2, [%3];"
                 :: "r"(sdst), "l"(gsrc), "r"(bytes), "r"(mbar) : "memory");
}
__device__ __forceinline__ void mbar_wait(unsigned a, unsigned ph) {
    asm volatile(
        "{\n\t.reg .pred P;\n\t"
        "WL%=:\n\t"
        "mbarrier.try_wait.parity.acquire.cta.shared::cta.b64 P, [%0], %1, 0x989680;\n\t"
        "@P bra WD%=;\n\t"
        "bra WL%=;\n\t"
        "WD%=:\n\t}"
        :: "r"(a), "r"(ph) : "memory");
}

// ---------------------------------------------------------------------------
// Prepass: weights -> fp16 XOR-swizzled GEMM tiles
// ---------------------------------------------------------------------------
__global__ void conv_w_h(const float* __restrict__ src, unsigned* __restrict__ dst, int n4)
{
    int i = blockIdx.x * blockDim.x + threadIdx.x;
    for (; i < n4; i += gridDim.x * blockDim.x) {
        int row = i >> 8;                // K=1024 -> 256 float4/row
        int col = (i & 255) * 4;
        float4 v = ((const float4*)src)[i];
        unsigned* base = dst + ((size_t)((row >> 7) * 64 + (col >> 4))) * GT_W + (row & 127) * 8;
        int rx = row & 7;
        int w0 = (col & 15) >> 1;        // 0,2,4,6
        base[w0 ^ rx]       = f22h2(v.x, v.y);
        base[(w0 + 1) ^ rx] = f22h2(v.z, v.w);
    }
}

// Prepass: gather concat(mem, rctx, utter) -> fp16 A tiles
__global__ void conv_kvin_h(const float* __restrict__ utter,
                            const float* __restrict__ rctx,
                            const float* __restrict__ mem)
{
    int i = blockIdx.x * blockDim.x + threadIdx.x;
    const int n4 = KVIN * D_DIM / 4;
    for (; i < n4; i += gridDim.x * blockDim.x) {
        int row = i >> 8;
        int col = (i & 255) * 4;
        const float4* s = (row < M_LEN)
            ? (const float4*)(mem + (size_t)row * D_DIM + col)
            : (row < MR)
            ? (const float4*)(rctx + (size_t)(row - M_LEN) * D_DIM + col)
            : (const float4*)(utter + (size_t)(row - MR) * D_DIM + col);
        float4 v = *s;
        unsigned* base = g_kvin_h + ((size_t)((row >> 7) * 64 + (col >> 4))) * GT_W + (row & 127) * 8;
        int rx = row & 7;
        int w0 = (col & 15) >> 1;
        base[w0 ^ rx]       = f22h2(v.x, v.y);
        base[(w0 + 1) ^ rx] = f22h2(v.z, v.w);
    }
}

// Prepass: left-context rows into fp16 K (row-major) and V^T (d-major)
__global__ void conv_lc(const float* __restrict__ lck, const float* __restrict__ lcv)
{
    int i = blockIdx.x * blockDim.x + threadIdx.x;
    const int n4 = L_LEN * D_DIM / 4;
    for (; i < n4; i += gridDim.x * blockDim.x) {
        int row = i >> 8;
        int col = (i & 255) * 4;
        int head = col >> 6, c = col & 63;
        int krow = MR + row;
        float4 k4 = *(const float4*)(lck + (size_t)row * D_DIM + col);
        float4 v4 = *(const float4*)(lcv + (size_t)row * D_DIM + col);
        // K: [head][krow][36w]
        unsigned* kb = g_key_h + ((size_t)head * KVLEN + krow) * KV_STR;
        kb[(c >> 1)]     = f22h2(k4.x, k4.y);
        kb[(c >> 1) + 1] = f22h2(k4.z, k4.w);
        // V^T: [head][tile][d][72h], element j = krow%64
        int tile = krow >> 6, j = krow & 63;
        __half* vb = g_val_h + (((size_t)head * NVTILES + tile) * 64 + c) * 72 + j;
        vb[0]      = __float2half_rn(v4.x);
        vb[72]     = __float2half_rn(v4.y);
        vb[144]    = __float2half_rn(v4.z);
        vb[216]    = __float2half_rn(v4.w);
    }
}

// ---------------------------------------------------------------------------
// FP16 GEMM, bulk-copy 4-stage pipeline: C = A @ W^T + bias   (unchanged)
// ---------------------------------------------------------------------------
#define GEMM_SMEM (8 * GT_W * 4 + 64)

template <int MODE>
__global__ __launch_bounds__(256, 2)
void gemm_h(const float* __restrict__ bias,
            float* __restrict__ C0,
            float* __restrict__ C1)
{
    extern __shared__ unsigned gsm[];
    unsigned* As = gsm;               // [4][1024]
    unsigned* Bs = gsm + 4 * GT_W;    // [4][1024]
    const unsigned mb0 = smaddr(gsm + 8 * GT_W);

    const int tid  = threadIdx.x;
    const int lane = tid & 31;
    const int warp = tid >> 5;
    const int wr   = warp & 3;
    const int wc   = warp >> 2;
    const int bm = blockIdx.y, bn = blockIdx.x;
    const int tig = lane & 3, grp = lane >> 2;

    const unsigned* Ab =
        (MODE == 0) ? g_kvin_h + (size_t)(bm + 4) * 64 * GT_W
      : (MODE == 1) ? g_kvin_h + (size_t)bm * 64 * GT_W
                    : g_attn_h + (size_t)bm * 64 * GT_W;
    const unsigned* Wb =
        ((MODE == 0) ? g_Wq_h : (MODE == 1) ? g_Wkv_h : g_Wo_h)
        + (size_t)bn * 64 * GT_W;

    if (tid == 0) {
        mbar_init(mb0); mbar_init(mb0 + 8); mbar_init(mb0 + 16); mbar_init(mb0 + 24);
    }
    __syncthreads();
    if (tid == 0) {
#pragma unroll
        for (int s = 0; s < 4; s++) {
            mbar_expect(mb0 + 8 * s, 2 * GT_B);
            bulk_g2s(smaddr(As + s * GT_W), Ab + (size_t)s * GT_W, GT_B, mb0 + 8 * s);
            bulk_g2s(smaddr(Bs + s * GT_W), Wb + (size_t)s * GT_W, GT_B, mb0 + 8 * s);
        }
    }

    float acc[2][8][4];
#pragma unroll
    for (int mt = 0; mt < 2; mt++)
#pragma unroll
        for (int nt = 0; nt < 8; nt++)
#pragma unroll
            for (int i = 0; i < 4; i++) acc[mt][nt][i] = 0.f;

    const int x0 = tig ^ grp;
    const int x1 = (tig + 4) ^ grp;

    for (int g = 0; g < NKT / 2; g++) {
#pragma unroll
        for (int sub = 0; sub < 2; sub++) {
            const int kt = 2 * g + sub;
            const int s  = kt & 3;
            mbar_wait(mb0 + 8 * s, (unsigned)((kt >> 2) & 1));

            const unsigned* Asl = As + s * GT_W;
            const unsigned* Bsl = Bs + s * GT_W;

            unsigned b[8][2];
#pragma unroll
            for (int nt = 0; nt < 8; nt++) {
                const unsigned* Bp = Bsl + (wc * 64 + nt * 8 + grp) * 8;
                b[nt][0] = Bp[x0];
                b[nt][1] = Bp[x1];
            }
#pragma unroll
            for (int mt = 0; mt < 2; mt++) {
                const unsigned* A0 = Asl + (wr * 32 + mt * 16 + grp) * 8;
                const unsigned* A1 = A0 + 64;
                unsigned a[4];
                a[0] = A0[x0]; a[1] = A1[x0]; a[2] = A0[x1]; a[3] = A1[x1];
#pragma unroll
                for (int nt = 0; nt < 8; nt++) mma_f16(acc[mt][nt], a, b[nt][0], b[nt][1]);
            }
        }
        __syncthreads();
        if (tid == 0 && 2 * g + 4 < NKT) {
#pragma unroll
            for (int sub = 0; sub < 2; sub++) {
                const int kt = 2 * g + 4 + sub;
                const int s  = kt & 3;
                mbar_expect(mb0 + 8 * s, 2 * GT_B);
                bulk_g2s(smaddr(As + s * GT_W), Ab + (size_t)kt * GT_W, GT_B, mb0 + 8 * s);
                bulk_g2s(smaddr(Bs + s * GT_W), Wb + (size_t)kt * GT_W, GT_B, mb0 + 8 * s);
            }
        }
    }

    // epilogue
#pragma unroll
    for (int mt = 0; mt < 2; mt++) {
#pragma unroll
        for (int nt = 0; nt < 8; nt++) {
            int col = bn * 128 + wc * 64 + nt * 8 + 2 * tig;
#pragma unroll
            for (int half = 0; half < 2; half++) {
                int row = bm * 128 + wr * 32 + mt * 16 + grp + half * 8;
                float v0 = acc[mt][nt][half * 2 + 0] + bias[col];
                float v1 = acc[mt][nt][half * 2 + 1] + bias[col + 1];
                if (MODE == 0) {
                    g_query_h[(size_t)row * 512 + (col >> 1)] =
                        f22h2(v0 * QSCALE, v1 * QSCALE);
                } else if (MODE == 1) {
                    int krow = (row < MR) ? row : row + L_LEN;
                    if (col < D_DIM) {
                        *(float2*)(C0 + (size_t)krow * D_DIM + col) = make_float2(v0, v1);
                        int head = col >> 6, c = col & 63;
                        g_key_h[((size_t)head * KVLEN + krow) * KV_STR + (c >> 1)] = f22h2(v0, v1);
                    } else {
                        int vc = col - D_DIM;
                        *(float2*)(C1 + (size_t)krow * D_DIM + vc) = make_float2(v0, v1);
                        int head = vc >> 6, c = vc & 63;
                        int tile = krow >> 6, j = krow & 63;
                        __half* vb = g_val_h + (((size_t)head * NVTILES + tile) * 64 + c) * 72 + j;
                        vb[0]  = __float2half_rn(v0);
                        vb[72] = __float2half_rn(v1);
                    }
                } else {
                    *(float2*)(C0 + (size_t)row * D_DIM + col) = make_float2(v0, v1);
                }
            }
        }
    }
}

// ---------------------------------------------------------------------------
// FP16 flash attention, fp16 accumulators (2x HMMA rate), register P,
// f16x2 softmax. 512 threads = 256 q rows of one head; 4-stage bulk pipeline.
// ---------------------------------------------------------------------------
#define AT_NT   NVTILES    // 60
#define ATT_SMEM (8 * KTILE_W * 4 + 64)

__global__ __launch_bounds__(512, 1)
void attn_mma(int dummy)
{
    extern __shared__ unsigned sm[];
    unsigned* Ks = sm;                           // [4][2304]
    unsigned* Vs = sm + 4 * KTILE_W;             // [4][2304]
    const unsigned mb0 = smaddr(sm + 8 * KTILE_W);

    const int h   = blockIdx.x;
    const int qb  = blockIdx.y;
    const int tid = threadIdx.x;
    const int lane = tid & 31;
    const int w    = tid >> 5;
    const int grp  = lane >> 2;
    const int tig  = lane & 3;

    const unsigned* ksrc = g_key_h + (size_t)h * KHEAD_W;
    const unsigned* vsrc = (const unsigned*)(g_val_h + (size_t)h * NVTILES * 64 * 72);

    if (tid == 0) {
        mbar_init(mb0); mbar_init(mb0 + 8); mbar_init(mb0 + 16); mbar_init(mb0 + 24);
    }
    __syncthreads();
    if (tid == 0) {
#pragma unroll
        for (int s = 0; s < 4; s++) {
            mbar_expect(mb0 + 8 * s, 2 * KTILE_W * 4);
            bulk_g2s(smaddr(Ks + s * KTILE_W), ksrc + (size_t)s * KTILE_W, KTILE_W * 4, mb0 + 8 * s);
            bulk_g2s(smaddr(Vs + s * KTILE_W), vsrc + (size_t)s * KTILE_W, KTILE_W * 4, mb0 + 8 * s);
        }
    }

    // Q fragments (fp16, pre-scaled, log2 domain)
    unsigned qa[4][4];
    {
        const unsigned* q0 = g_query_h + (size_t)(qb * 256 + w * 16 + grp) * 512 + h * 32;
        const unsigned* q1 = q0 + 8 * 512;
#pragma unroll
        for (int kb = 0; kb < 4; kb++) {
            qa[kb][0] = q0[kb * 8 + tig];
            qa[kb][1] = q1[kb * 8 + tig];
            qa[kb][2] = q0[kb * 8 + tig + 4];
            qa[kb][3] = q1[kb * 8 + tig + 4];
        }
    }

    float acc[8][4];
#pragma unroll
    for (int nt = 0; nt < 8; nt++)
#pragma unroll
        for (int i = 0; i < 4; i++) acc[nt][i] = 0.f;
    float m0 = -1e30f, m1 = -1e30f, l0 = 0.f, l1 = 0.f;

    for (int g = 0; g < AT_NT / 2; g++) {
#pragma unroll
        for (int sub = 0; sub < 2; sub++) {
            const int t = 2 * g + sub;
            const int s = t & 3;
            mbar_wait(mb0 + 8 * s, (unsigned)((t >> 2) & 1));

            const unsigned* Kc = Ks + s * KTILE_W;
            const unsigned* Vc = Vs + s * KTILE_W;

            // ---- S = Q K^T, fp16 accumulate (log2 domain) ----
            unsigned sch[8][2];
#pragma unroll
            for (int nt = 0; nt < 8; nt++) { sch[nt][0] = 0u; sch[nt][1] = 0u; }
#pragma unroll
            for (int kb = 0; kb < 4; kb++) {
#pragma unroll
                for (int nt = 0; nt < 8; nt++) {
                    const unsigned* Kp = Kc + (nt * 8 + grp) * KV_STR + kb * 8;
                    mma_f16h(sch[nt], qa[kb], Kp[tig], Kp[tig + 4]);
                }
            }

            // ---- online softmax (packed f16x2) ----
            unsigned mx0 = sch[0][0], mx1 = sch[0][1];
#pragma unroll
            for (int nt = 1; nt < 8; nt++) {
                mx0 = hmax2(mx0, sch[nt][0]);
                mx1 = hmax2(mx1, sch[nt][1]);
            }
            float2 fm0 = h22f2(mx0), fm1 = h22f2(mx1);
            float mt0 = fmaxf(fm0.x, fm0.y);
            float mt1 = fmaxf(fm1.x, fm1.y);
            mt0 = fmaxf(mt0, __shfl_xor_sync(0xffffffff, mt0, 1));
            mt0 = fmaxf(mt0, __shfl_xor_sync(0xffffffff, mt0, 2));
            mt1 = fmaxf(mt1, __shfl_xor_sync(0xffffffff, mt1, 1));
            mt1 = fmaxf(mt1, __shfl_xor_sync(0xffffffff, mt1, 2));

            float mn0 = fmaxf(m0, mt0), mn1 = fmaxf(m1, mt1);
            float c0 = exp2f(m0 - mn0), c1 = exp2f(m1 - mn1);
            l0 *= c0; l1 *= c1;
            m0 = mn0; m1 = mn1;

            const unsigned mn0h = f22h2(mn0, mn0);
            const unsigned mn1h = f22h2(mn1, mn1);
            unsigned ph[8][2];
#pragma unroll
            for (int nt = 0; nt < 8; nt++) {
                ph[nt][0] = ex2h2(hsub2(sch[nt][0], mn0h));
                ph[nt][1] = ex2h2(hsub2(sch[nt][1], mn1h));
            }

            // l accumulation: HADD2 tree over nt, then to fp32
            {
                unsigned s00 = hadd2u(hadd2u(ph[0][0], ph[1][0]), hadd2u(ph[2][0], ph[3][0]));
                unsigned s01 = hadd2u(hadd2u(ph[4][0], ph[5][0]), hadd2u(ph[6][0], ph[7][0]));
                unsigned s10 = hadd2u(hadd2u(ph[0][1], ph[1][1]), hadd2u(ph[2][1], ph[3][1]));
                unsigned s11 = hadd2u(hadd2u(ph[4][1], ph[5][1]), hadd2u(ph[6][1], ph[7][1]));
                float2 f0 = h22f2(s00), f1 = h22f2(s01);
                float2 f2 = h22f2(s10), f3 = h22f2(s11);
                l0 += (f0.x + f0.y) + (f1.x + f1.y);
                l1 += (f2.x + f2.y) + (f3.x + f3.y);
            }

            // ---- per-tile P @ V in fp16 acc, merge into fp32 master ----
            unsigned pacc[8][2];
#pragma unroll
            for (int nt = 0; nt < 8; nt++) { pacc[nt][0] = 0u; pacc[nt][1] = 0u; }
#pragma unroll
            for (int kb = 0; kb < 4; kb++) {
                unsigned a[4];
                a[0] = ph[2 * kb][0];
                a[1] = ph[2 * kb][1];
                a[2] = ph[2 * kb + 1][0];
                a[3] = ph[2 * kb + 1][1];
#pragma unroll
                for (int nt = 0; nt < 8; nt++) {
                    const unsigned* Vp = Vc + (nt * 8 + grp) * KV_STR + kb * 8;
                    mma_f16h(pacc[nt], a, Vp[tig], Vp[tig + 4]);
                }
            }
#pragma unroll
            for (int nt = 0; nt < 8; nt++) {
                float2 lo = h22f2(pacc[nt][0]);
                float2 hi = h22f2(pacc[nt][1]);
                acc[nt][0] = acc[nt][0] * c0 + lo.x;
                acc[nt][1] = acc[nt][1] * c0 + lo.y;
                acc[nt][2] = acc[nt][2] * c1 + hi.x;
                acc[nt][3] = acc[nt][3] * c1 + hi.y;
            }
        }

        __syncthreads();
        if (tid == 0 && 2 * g + 4 < AT_NT) {
#pragma unroll
            for (int sub = 0; sub < 2; sub++) {
                const int t = 2 * g + 4 + sub;
                const int s = t & 3;
                mbar_expect(mb0 + 8 * s, 2 * KTILE_W * 4);
                bulk_g2s(smaddr(Ks + s * KTILE_W), ksrc + (size_t)t * KTILE_W, KTILE_W * 4, mb0 + 8 * s);
                bulk_g2s(smaddr(Vs + s * KTILE_W), vsrc + (size_t)t * KTILE_W, KTILE_W * 4, mb0 + 8 * s);
            }
        }
    }

    // ---- finalize: write fp16 XOR-swizzled A-tile layout for gemm_h<2> ----
    l0 += __shfl_xor_sync(0xffffffff, l0, 1);
    l0 += __shfl_xor_sync(0xffffffff, l0, 2);
    l1 += __shfl_xor_sync(0xffffffff, l1, 1);
    l1 += __shfl_xor_sync(0xffffffff, l1, 2);
    float inv0 = 1.f / l0, inv1 = 1.f / l1;

    int r0 = qb * 256 + w * 16 + grp;
    int r1 = r0 + 8;
#pragma unroll
    for (int nt = 0; nt < 8; nt++) {
        int col = h * HDIM + nt * 8 + 2 * tig;
        int kt = col >> 4;
        int wd = (col & 15) >> 1;
        {
            unsigned* base = g_attn_h + ((size_t)((r0 >> 7) * 64 + kt)) * GT_W + (r0 & 127) * 8;
            base[wd ^ (r0 & 7)] = f22h2(acc[nt][0] * inv0, acc[nt][1] * inv0);
        }
        {
            unsigned* base = g_attn_h + ((size_t)((r1 >> 7) * 64 + kt)) * GT_W + (r1 & 127) * 8;
            base[wd ^ (r1 & 7)] = f22h2(acc[nt][2] * inv1, acc[nt][3] * inv1);
        }
    }
}

// ---------------------------------------------------------------------------
extern "C" void kernel_launch(void* const* d_in, const int* in_sizes, int n_in,
                              void* d_out, int out_size)
{
    const float* utter = (const float*)d_in[0];
    const float* rctx  = (const float*)d_in[1];
    const float* mem   = (const float*)d_in[2];
    const float* lck   = (const float*)d_in[3];
    const float* lcv   = (const float*)d_in[4];
    const float* Wq    = (const float*)d_in[5];
    const float* bq    = (const float*)d_in[6];
    const float* Wkv   = (const float*)d_in[7];
    const float* bkv   = (const float*)d_in[8];
    const float* Wo    = (const float*)d_in[9];
    const float* bo    = (const float*)d_in[10];

    float* out = (float*)d_out;                       // [2304, 1024]
    float* key = out + (size_t)QLEN * D_DIM;          // [3840, 1024]
    float* val = key + (size_t)KVLEN * D_DIM;         // [3840, 1024]

    static cudaStream_t s1 = nullptr;
    static cudaEvent_t eFork = nullptr, eP1 = nullptr, eG1 = nullptr, eTail = nullptr;
    if (!s1) {
        cudaFuncSetAttribute(attn_mma, cudaFuncAttributeMaxDynamicSharedMemorySize, ATT_SMEM);
        cudaFuncSetAttribute(gemm_h<0>, cudaFuncAttributeMaxDynamicSharedMemorySize, GEMM_SMEM);
        cudaFuncSetAttribute(gemm_h<1>, cudaFuncAttributeMaxDynamicSharedMemorySize, GEMM_SMEM);
        cudaFuncSetAttribute(gemm_h<2>, cudaFuncAttributeMaxDynamicSharedMemorySize, GEMM_SMEM);
        cudaStreamCreateWithFlags(&s1, cudaStreamNonBlocking);
        cudaEventCreateWithFlags(&eFork, cudaEventDisableTiming);
        cudaEventCreateWithFlags(&eP1,   cudaEventDisableTiming);
        cudaEventCreateWithFlags(&eG1,   cudaEventDisableTiming);
        cudaEventCreateWithFlags(&eTail, cudaEventDisableTiming);
    }

    unsigned *wq_p, *wkv_p, *wo_p;
    cudaGetSymbolAddress((void**)&wq_p,  g_Wq_h);
    cudaGetSymbolAddress((void**)&wkv_p, g_Wkv_h);
    cudaGetSymbolAddress((void**)&wo_p,  g_Wo_h);

    // ---- fork s1 off the capture (legacy) stream ----
    cudaEventRecord(eFork, 0);
    cudaStreamWaitEvent(s1, eFork, 0);

    // ---- s0 chain: kvin -> Wq -> gemm0 (q proj) ----
    conv_kvin_h<<<512, 256, 0, 0>>>(utter, rctx, mem);
    cudaEventRecord(eP1, 0);                       // kvin ready
    conv_w_h<<<256, 256, 0, 0>>>(Wq, wq_p, D_DIM * D_DIM / 4);
    gemm_h<0><<<dim3(D_DIM / 128, QLEN / 128), 256, GEMM_SMEM, 0>>>(bq, nullptr, nullptr);

    // ---- s1 chain: Wkv -> lc -> (wait kvin) gemm1 -> Wo -> memcpys ----
    conv_w_h<<<512, 256, 0, s1>>>(Wkv, wkv_p, 2 * D_DIM * D_DIM / 4);
    conv_lc<<<256, 256, 0, s1>>>(lck, lcv);
    cudaStreamWaitEvent(s1, eP1, 0);
    gemm_h<1><<<dim3(2 * D_DIM / 128, KVIN / 128), 256, GEMM_SMEM, s1>>>(bkv, key, val);
    cudaEventRecord(eG1, s1);                      // kv + lc ready for attention
    conv_w_h<<<256, 256, 0, s1>>>(Wo, wo_p, D_DIM * D_DIM / 4);
    cudaMemcpyAsync(key + (size_t)MR * D_DIM, lck,
                    (size_t)L_LEN * D_DIM * sizeof(float),
                    cudaMemcpyDeviceToDevice, s1);
    cudaMemcpyAsync(val + (size_t)MR * D_DIM, lcv,
                    (size_t)L_LEN * D_DIM * sizeof(float),
                    cudaMemcpyDeviceToDevice, s1);
    cudaEventRecord(eTail, s1);                    // Wo + d_out splices done

    // ---- s0: attention (overlaps conv_wo + memcpys), then join + gemm2 ----
    cudaStreamWaitEvent(0, eG1, 0);
    attn_mma<<<dim3(NHEAD, QLEN / 256), 512, ATT_SMEM, 0>>>(0);
    cudaStreamWaitEvent(0, eTail, 0);              // join s1 back into capture stream
    gemm_h<2><<<dim3(D_DIM / 128, QLEN / 128), 256, GEMM_SMEM, 0>>>(bo, out, nullptr);
}

// round 17
// speedup vs baseline: 1.0118x; 1.0118x over previous
#include <cuda_runtime.h>
#include <cuda_fp16.h>

// Problem dims
#define U_LEN 2048
#define R_LEN 256
#define L_LEN 1024
#define M_LEN 512
#define D_DIM 1024
#define NHEAD 16
#define HDIM  64
#define QLEN  (U_LEN + R_LEN)                   // 2304
#define KVLEN (M_LEN + R_LEN + L_LEN + U_LEN)   // 3840
#define MR    (M_LEN + R_LEN)                   // 768
#define KVIN  (MR + U_LEN)                      // 2816

// GEMM tiles: 128 rows x 16 halves = 1024 words (4KB), XOR swizzle w^(r&7)
#define GT_W 1024
#define GT_B 4096
#define NKT  64

// Attention K / V^T: rows of 64 halves = 32 words + 4 pad = stride 36 words
#define KV_STR   36
#define KTILE_W  (64 * KV_STR)       // 2304 words = 9216 B
#define KHEAD_W  (KVLEN * KV_STR)    // 138240 words
#define NVTILES  (KVLEN / 64)        // 60

// log2(e) folded into q scaling
#define QSCALE (0.125f * 1.4426950408889634f)

// Scratch (no cudaMalloc allowed)
__device__ __align__(16) unsigned g_kvin_h [22 * 64 * GT_W];
__device__ __align__(16) unsigned g_attn_h [18 * 64 * GT_W];
__device__ __align__(16) unsigned g_Wq_h   [ 8 * 64 * GT_W];
__device__ __align__(16) unsigned g_Wkv_h  [16 * 64 * GT_W];
__device__ __align__(16) unsigned g_Wo_h   [ 8 * 64 * GT_W];
__device__ __align__(16) unsigned g_query_h[QLEN * 512];          // fp16 row-major
__device__ __align__(16) unsigned g_key_h  [NHEAD * KHEAD_W];     // [head][row][36w]
__device__ __align__(16) __half   g_val_h  [NHEAD * NVTILES * 64 * 72]; // [head][tile][d][72h]

// ---------------------------------------------------------------------------
// helpers
// ---------------------------------------------------------------------------
__device__ __forceinline__ unsigned f22h2(float a, float b) {
    __half2 h = __floats2half2_rn(a, b);
    return *reinterpret_cast<unsigned*>(&h);
}

// pack (lo=a, hi=b) and exp2 both halves in one MUFU op
__device__ __forceinline__ unsigned exp2_h2(float a, float b) {
    unsigned p, r;
    asm("cvt.rn.f16x2.f32 %0, %2, %1;" : "=r"(p) : "f"(a), "f"(b));
    asm("ex2.approx.f16x2 %0, %1;" : "=r"(r) : "r"(p));
    return r;
}

__device__ __forceinline__ unsigned hadd2u(unsigned a, unsigned b) {
    unsigned r;
    asm("add.f16x2 %0, %1, %2;" : "=r"(r) : "r"(a), "r"(b));
    return r;
}

__device__ __forceinline__ void mma_f16(float* d, const unsigned* a, unsigned b0, unsigned b1) {
    asm volatile(
        "mma.sync.aligned.m16n8k16.row.col.f32.f16.f16.f32 "
        "{%0,%1,%2,%3}, {%4,%5,%6,%7}, {%8,%9}, {%0,%1,%2,%3};"
        : "+f"(d[0]), "+f"(d[1]), "+f"(d[2]), "+f"(d[3])
        : "r"(a[0]), "r"(a[1]), "r"(a[2]), "r"(a[3]), "r"(b0), "r"(b1));
}

__device__ __forceinline__ unsigned smaddr(const void* p) {
    return (unsigned)__cvta_generic_to_shared(p);
}
__device__ __forceinline__ void mbar_init(unsigned a) {
    asm volatile("mbarrier.init.shared.b64 [%0], 1;" :: "r"(a) : "memory");
}
__device__ __forceinline__ void mbar_expect(unsigned a, unsigned tx) {
    asm volatile("mbarrier.arrive.expect_tx.shared.b64 _, [%0], %1;" :: "r"(a), "r"(tx) : "memory");
}
__device__ __forceinline__ void bulk_g2s(unsigned sdst, const void* gsrc, unsigned bytes, unsigned mbar) {
    asm volatile("cp.async.bulk.shared::cta.global.mbarrier::complete_tx::bytes [%0], [%1], %2, [%3];"
                 :: "r"(sdst), "l"(gsrc), "r"(bytes), "r"(mbar) : "memory");
}
__device__ __forceinline__ void mbar_wait(unsigned a, unsigned ph) {
    asm volatile(
        "{\n\t.reg .pred P;\n\t"
        "WL%=:\n\t"
        "mbarrier.try_wait.parity.acquire.cta.shared::cta.b64 P, [%0], %1, 0x989680;\n\t"
        "@P bra WD%=;\n\t"
        "bra WL%=;\n\t"
        "WD%=:\n\t}"
        :: "r"(a), "r"(ph) : "memory");
}

// ---------------------------------------------------------------------------
// Prepass: weights -> fp16 XOR-swizzled GEMM tiles
// ---------------------------------------------------------------------------
__global__ void conv_w_h(const float* __restrict__ src, unsigned* __restrict__ dst, int n4)
{
    int i = blockIdx.x * blockDim.x + threadIdx.x;
    for (; i < n4; i += gridDim.x * blockDim.x) {
        int row = i >> 8;                // K=1024 -> 256 float4/row
        int col = (i & 255) * 4;
        float4 v = ((const float4*)src)[i];
        unsigned* base = dst + ((size_t)((row >> 7) * 64 + (col >> 4))) * GT_W + (row & 127) * 8;
        int rx = row & 7;
        int w0 = (col & 15) >> 1;        // 0,2,4,6
        base[w0 ^ rx]       = f22h2(v.x, v.y);
        base[(w0 + 1) ^ rx] = f22h2(v.z, v.w);
    }
}

// Prepass: gather concat(mem, rctx, utter) -> fp16 A tiles
__global__ void conv_kvin_h(const float* __restrict__ utter,
                            const float* __restrict__ rctx,
                            const float* __restrict__ mem)
{
    int i = blockIdx.x * blockDim.x + threadIdx.x;
    const int n4 = KVIN * D_DIM / 4;
    for (; i < n4; i += gridDim.x * blockDim.x) {
        int row = i >> 8;
        int col = (i & 255) * 4;
        const float4* s = (row < M_LEN)
            ? (const float4*)(mem + (size_t)row * D_DIM + col)
            : (row < MR)
            ? (const float4*)(rctx + (size_t)(row - M_LEN) * D_DIM + col)
            : (const float4*)(utter + (size_t)(row - MR) * D_DIM + col);
        float4 v = *s;
        unsigned* base = g_kvin_h + ((size_t)((row >> 7) * 64 + (col >> 4))) * GT_W + (row & 127) * 8;
        int rx = row & 7;
        int w0 = (col & 15) >> 1;
        base[w0 ^ rx]       = f22h2(v.x, v.y);
        base[(w0 + 1) ^ rx] = f22h2(v.z, v.w);
    }
}

// Prepass: left-context rows into fp16 K (row-major) and V^T (d-major)
__global__ void conv_lc(const float* __restrict__ lck, const float* __restrict__ lcv)
{
    int i = blockIdx.x * blockDim.x + threadIdx.x;
    const int n4 = L_LEN * D_DIM / 4;
    for (; i < n4; i += gridDim.x * blockDim.x) {
        int row = i >> 8;
        int col = (i & 255) * 4;
        int head = col >> 6, c = col & 63;
        int krow = MR + row;
        float4 k4 = *(const float4*)(lck + (size_t)row * D_DIM + col);
        float4 v4 = *(const float4*)(lcv + (size_t)row * D_DIM + col);
        // K: [head][krow][36w]
        unsigned* kb = g_key_h + ((size_t)head * KVLEN + krow) * KV_STR;
        kb[(c >> 1)]     = f22h2(k4.x, k4.y);
        kb[(c >> 1) + 1] = f22h2(k4.z, k4.w);
        // V^T: [head][tile][d][72h], element j = krow%64
        int tile = krow >> 6, j = krow & 63;
        __half* vb = g_val_h + (((size_t)head * NVTILES + tile) * 64 + c) * 72 + j;
        vb[0]      = __float2half_rn(v4.x);
        vb[72]     = __float2half_rn(v4.y);
        vb[144]    = __float2half_rn(v4.z);
        vb[216]    = __float2half_rn(v4.w);
    }
}

// ---------------------------------------------------------------------------
// FP16 GEMM, bulk-copy 4-stage pipeline: C = A @ W^T + bias   (unchanged R12)
// ---------------------------------------------------------------------------
#define GEMM_SMEM (8 * GT_W * 4 + 64)

template <int MODE>
__global__ __launch_bounds__(256, 2)
void gemm_h(const float* __restrict__ bias,
            float* __restrict__ C0,
            float* __restrict__ C1)
{
    extern __shared__ unsigned gsm[];
    unsigned* As = gsm;               // [4][1024]
    unsigned* Bs = gsm + 4 * GT_W;    // [4][1024]
    const unsigned mb0 = smaddr(gsm + 8 * GT_W);

    const int tid  = threadIdx.x;
    const int lane = tid & 31;
    const int warp = tid >> 5;
    const int wr   = warp & 3;
    const int wc   = warp >> 2;
    const int bm = blockIdx.y, bn = blockIdx.x;
    const int tig = lane & 3, grp = lane >> 2;

    const unsigned* Ab =
        (MODE == 0) ? g_kvin_h + (size_t)(bm + 4) * 64 * GT_W
      : (MODE == 1) ? g_kvin_h + (size_t)bm * 64 * GT_W
                    : g_attn_h + (size_t)bm * 64 * GT_W;
    const unsigned* Wb =
        ((MODE == 0) ? g_Wq_h : (MODE == 1) ? g_Wkv_h : g_Wo_h)
        + (size_t)bn * 64 * GT_W;

    if (tid == 0) {
        mbar_init(mb0); mbar_init(mb0 + 8); mbar_init(mb0 + 16); mbar_init(mb0 + 24);
    }
    __syncthreads();
    if (tid == 0) {
#pragma unroll
        for (int s = 0; s < 4; s++) {
            mbar_expect(mb0 + 8 * s, 2 * GT_B);
            bulk_g2s(smaddr(As + s * GT_W), Ab + (size_t)s * GT_W, GT_B, mb0 + 8 * s);
            bulk_g2s(smaddr(Bs + s * GT_W), Wb + (size_t)s * GT_W, GT_B, mb0 + 8 * s);
        }
    }

    float acc[2][8][4];
#pragma unroll
    for (int mt = 0; mt < 2; mt++)
#pragma unroll
        for (int nt = 0; nt < 8; nt++)
#pragma unroll
            for (int i = 0; i < 4; i++) acc[mt][nt][i] = 0.f;

    const int x0 = tig ^ grp;
    const int x1 = (tig + 4) ^ grp;

    for (int g = 0; g < NKT / 2; g++) {
#pragma unroll
        for (int sub = 0; sub < 2; sub++) {
            const int kt = 2 * g + sub;
            const int s  = kt & 3;
            mbar_wait(mb0 + 8 * s, (unsigned)((kt >> 2) & 1));

            const unsigned* Asl = As + s * GT_W;
            const unsigned* Bsl = Bs + s * GT_W;

            unsigned b[8][2];
#pragma unroll
            for (int nt = 0; nt < 8; nt++) {
                const unsigned* Bp = Bsl + (wc * 64 + nt * 8 + grp) * 8;
                b[nt][0] = Bp[x0];
                b[nt][1] = Bp[x1];
            }
#pragma unroll
            for (int mt = 0; mt < 2; mt++) {
                const unsigned* A0 = Asl + (wr * 32 + mt * 16 + grp) * 8;
                const unsigned* A1 = A0 + 64;
                unsigned a[4];
                a[0] = A0[x0]; a[1] = A1[x0]; a[2] = A0[x1]; a[3] = A1[x1];
#pragma unroll
                for (int nt = 0; nt < 8; nt++) mma_f16(acc[mt][nt], a, b[nt][0], b[nt][1]);
            }
        }
        __syncthreads();
        if (tid == 0 && 2 * g + 4 < NKT) {
#pragma unroll
            for (int sub = 0; sub < 2; sub++) {
                const int kt = 2 * g + 4 + sub;
                const int s  = kt & 3;
                mbar_expect(mb0 + 8 * s, 2 * GT_B);
                bulk_g2s(smaddr(As + s * GT_W), Ab + (size_t)kt * GT_W, GT_B, mb0 + 8 * s);
                bulk_g2s(smaddr(Bs + s * GT_W), Wb + (size_t)kt * GT_W, GT_B, mb0 + 8 * s);
            }
        }
    }

    // epilogue
#pragma unroll
    for (int mt = 0; mt < 2; mt++) {
#pragma unroll
        for (int nt = 0; nt < 8; nt++) {
            int col = bn * 128 + wc * 64 + nt * 8 + 2 * tig;
#pragma unroll
            for (int half = 0; half < 2; half++) {
                int row = bm * 128 + wr * 32 + mt * 16 + grp + half * 8;
                float v0 = acc[mt][nt][half * 2 + 0] + bias[col];
                float v1 = acc[mt][nt][half * 2 + 1] + bias[col + 1];
                if (MODE == 0) {
                    g_query_h[(size_t)row * 512 + (col >> 1)] =
                        f22h2(v0 * QSCALE, v1 * QSCALE);
                } else if (MODE == 1) {
                    int krow = (row < MR) ? row : row + L_LEN;
                    if (col < D_DIM) {
                        *(float2*)(C0 + (size_t)krow * D_DIM + col) = make_float2(v0, v1);
                        int head = col >> 6, c = col & 63;
                        g_key_h[((size_t)head * KVLEN + krow) * KV_STR + (c >> 1)] = f22h2(v0, v1);
                    } else {
                        int vc = col - D_DIM;
                        *(float2*)(C1 + (size_t)krow * D_DIM + vc) = make_float2(v0, v1);
                        int head = vc >> 6, c = vc & 63;
                        int tile = krow >> 6, j = krow & 63;
                        __half* vb = g_val_h + (((size_t)head * NVTILES + tile) * 64 + c) * 72 + j;
                        vb[0]  = __float2half_rn(v0);
                        vb[72] = __float2half_rn(v1);
                    }
                } else {
                    *(float2*)(C0 + (size_t)row * D_DIM + col) = make_float2(v0, v1);
                }
            }
        }
    }
}

// ---------------------------------------------------------------------------
// FP16 flash attention: 256 threads = 128 q rows, 2 CTAs/SM for phase overlap.
// Register-resident P, f16x2 exp2, fp32 accumulators. 4-stage bulk pipeline.
// ---------------------------------------------------------------------------
#define AT_NT   NVTILES    // 60
#define ATT_SMEM (8 * KTILE_W * 4 + 64)

__global__ __launch_bounds__(256, 2)
void attn_mma(int dummy)
{
    extern __shared__ unsigned sm[];
    unsigned* Ks = sm;                           // [4][2304]
    unsigned* Vs = sm + 4 * KTILE_W;             // [4][2304]
    const unsigned mb0 = smaddr(sm + 8 * KTILE_W);

    const int h   = blockIdx.x;
    const int qb  = blockIdx.y;
    const int tid = threadIdx.x;
    const int lane = tid & 31;
    const int w    = tid >> 5;              // 0..7
    const int grp  = lane >> 2;
    const int tig  = lane & 3;

    const unsigned* ksrc = g_key_h + (size_t)h * KHEAD_W;
    const unsigned* vsrc = (const unsigned*)(g_val_h + (size_t)h * NVTILES * 64 * 72);

    if (tid == 0) {
        mbar_init(mb0); mbar_init(mb0 + 8); mbar_init(mb0 + 16); mbar_init(mb0 + 24);
    }
    __syncthreads();
    if (tid == 0) {
#pragma unroll
        for (int s = 0; s < 4; s++) {
            mbar_expect(mb0 + 8 * s, 2 * KTILE_W * 4);
            bulk_g2s(smaddr(Ks + s * KTILE_W), ksrc + (size_t)s * KTILE_W, KTILE_W * 4, mb0 + 8 * s);
            bulk_g2s(smaddr(Vs + s * KTILE_W), vsrc + (size_t)s * KTILE_W, KTILE_W * 4, mb0 + 8 * s);
        }
    }

    // Q fragments (fp16, pre-scaled, log2 domain)
    unsigned qa[4][4];
    {
        const unsigned* q0 = g_query_h + (size_t)(qb * 128 + w * 16 + grp) * 512 + h * 32;
        const unsigned* q1 = q0 + 8 * 512;
#pragma unroll
        for (int kb = 0; kb < 4; kb++) {
            qa[kb][0] = q0[kb * 8 + tig];
            qa[kb][1] = q1[kb * 8 + tig];
            qa[kb][2] = q0[kb * 8 + tig + 4];
            qa[kb][3] = q1[kb * 8 + tig + 4];
        }
    }

    float acc[8][4];
#pragma unroll
    for (int nt = 0; nt < 8; nt++)
#pragma unroll
        for (int i = 0; i < 4; i++) acc[nt][i] = 0.f;
    float m0 = -1e30f, m1 = -1e30f, l0 = 0.f, l1 = 0.f;

    for (int g = 0; g < AT_NT / 2; g++) {
#pragma unroll
        for (int sub = 0; sub < 2; sub++) {
            const int t = 2 * g + sub;
            const int s = t & 3;
            mbar_wait(mb0 + 8 * s, (unsigned)((t >> 2) & 1));

            const unsigned* Kc = Ks + s * KTILE_W;
            const unsigned* Vc = Vs + s * KTILE_W;

            // ---- S = Q K^T (log2 domain) ----
            float sc[8][4];
#pragma unroll
            for (int nt = 0; nt < 8; nt++)
#pragma unroll
                for (int i = 0; i < 4; i++) sc[nt][i] = 0.f;
#pragma unroll
            for (int kb = 0; kb < 4; kb++) {
#pragma unroll
                for (int nt = 0; nt < 8; nt++) {
                    const unsigned* Kp = Kc + (nt * 8 + grp) * KV_STR + kb * 8;
                    mma_f16(sc[nt], qa[kb], Kp[tig], Kp[tig + 4]);
                }
            }

            // ---- online softmax (f16x2 exp2, P in registers) ----
            float mt0 = -1e30f, mt1 = -1e30f;
#pragma unroll
            for (int nt = 0; nt < 8; nt++) {
                mt0 = fmaxf(mt0, fmaxf(sc[nt][0], sc[nt][1]));
                mt1 = fmaxf(mt1, fmaxf(sc[nt][2], sc[nt][3]));
            }
            mt0 = fmaxf(mt0, __shfl_xor_sync(0xffffffff, mt0, 1));
            mt0 = fmaxf(mt0, __shfl_xor_sync(0xffffffff, mt0, 2));
            mt1 = fmaxf(mt1, __shfl_xor_sync(0xffffffff, mt1, 1));
            mt1 = fmaxf(mt1, __shfl_xor_sync(0xffffffff, mt1, 2));

            float mn0 = fmaxf(m0, mt0), mn1 = fmaxf(m1, mt1);
            float c0 = exp2f(m0 - mn0), c1 = exp2f(m1 - mn1);
            l0 *= c0; l1 *= c1;
            m0 = mn0; m1 = mn1;

            unsigned ph[8][2];
#pragma unroll
            for (int nt = 0; nt < 8; nt++) {
                ph[nt][0] = exp2_h2(sc[nt][0] - mn0, sc[nt][1] - mn0);
                ph[nt][1] = exp2_h2(sc[nt][2] - mn1, sc[nt][3] - mn1);
                acc[nt][0] *= c0; acc[nt][1] *= c0;
                acc[nt][2] *= c1; acc[nt][3] *= c1;
            }

            // l accumulation: HADD2 tree over nt, then to fp32
            {
                unsigned s00 = hadd2u(hadd2u(ph[0][0], ph[1][0]), hadd2u(ph[2][0], ph[3][0]));
                unsigned s01 = hadd2u(hadd2u(ph[4][0], ph[5][0]), hadd2u(ph[6][0], ph[7][0]));
                unsigned s10 = hadd2u(hadd2u(ph[0][1], ph[1][1]), hadd2u(ph[2][1], ph[3][1]));
                unsigned s11 = hadd2u(hadd2u(ph[4][1], ph[5][1]), hadd2u(ph[6][1], ph[7][1]));
                float2 f0 = __half22float2(*reinterpret_cast<__half2*>(&s00));
                float2 f1 = __half22float2(*reinterpret_cast<__half2*>(&s01));
                float2 f2 = __half22float2(*reinterpret_cast<__half2*>(&s10));
                float2 f3 = __half22float2(*reinterpret_cast<__half2*>(&s11));
                l0 += (f0.x + f0.y) + (f1.x + f1.y);
                l1 += (f2.x + f2.y) + (f3.x + f3.y);
            }

            // ---- acc += P @ V  (P a-frags direct from registers) ----
#pragma unroll
            for (int kb = 0; kb < 4; kb++) {
                unsigned a[4];
                a[0] = ph[2 * kb][0];
                a[1] = ph[2 * kb][1];
                a[2] = ph[2 * kb + 1][0];
                a[3] = ph[2 * kb + 1][1];
#pragma unroll
                for (int nt = 0; nt < 8; nt++) {
                    const unsigned* Vp = Vc + (nt * 8 + grp) * KV_STR + kb * 8;
                    mma_f16(acc[nt], a, Vp[tig], Vp[tig + 4]);
                }
            }
        }

        __syncthreads();
        if (tid == 0 && 2 * g + 4 < AT_NT) {
#pragma unroll
            for (int sub = 0; sub < 2; sub++) {
                const int t = 2 * g + 4 + sub;
                const int s = t & 3;
                mbar_expect(mb0 + 8 * s, 2 * KTILE_W * 4);
                bulk_g2s(smaddr(Ks + s * KTILE_W), ksrc + (size_t)t * KTILE_W, KTILE_W * 4, mb0 + 8 * s);
                bulk_g2s(smaddr(Vs + s * KTILE_W), vsrc + (size_t)t * KTILE_W, KTILE_W * 4, mb0 + 8 * s);
            }
        }
    }

    // ---- finalize: write fp16 XOR-swizzled A-tile layout for gemm_h<2> ----
    l0 += __shfl_xor_sync(0xffffffff, l0, 1);
    l0 += __shfl_xor_sync(0xffffffff, l0, 2);
    l1 += __shfl_xor_sync(0xffffffff, l1, 1);
    l1 += __shfl_xor_sync(0xffffffff, l1, 2);
    float inv0 = 1.f / l0, inv1 = 1.f / l1;

    int r0 = qb * 128 + w * 16 + grp;
    int r1 = r0 + 8;
#pragma unroll
    for (int nt = 0; nt < 8; nt++) {
        int col = h * HDIM + nt * 8 + 2 * tig;
        int kt = col >> 4;
        int wd = (col & 15) >> 1;
        {
            unsigned* base = g_attn_h + ((size_t)((r0 >> 7) * 64 + kt)) * GT_W + (r0 & 127) * 8;
            base[wd ^ (r0 & 7)] = f22h2(acc[nt][0] * inv0, acc[nt][1] * inv0);
        }
        {
            unsigned* base = g_attn_h + ((size_t)((r1 >> 7) * 64 + kt)) * GT_W + (r1 & 127) * 8;
            base[wd ^ (r1 & 7)] = f22h2(acc[nt][2] * inv1, acc[nt][3] * inv1);
        }
    }
}

// ---------------------------------------------------------------------------
extern "C" void kernel_launch(void* const* d_in, const int* in_sizes, int n_in,
                              void* d_out, int out_size)
{
    const float* utter = (const float*)d_in[0];
    const float* rctx  = (const float*)d_in[1];
    const float* mem   = (const float*)d_in[2];
    const float* lck   = (const float*)d_in[3];
    const float* lcv   = (const float*)d_in[4];
    const float* Wq    = (const float*)d_in[5];
    const float* bq    = (const float*)d_in[6];
    const float* Wkv   = (const float*)d_in[7];
    const float* bkv   = (const float*)d_in[8];
    const float* Wo    = (const float*)d_in[9];
    const float* bo    = (const float*)d_in[10];

    float* out = (float*)d_out;                       // [2304, 1024]
    float* key = out + (size_t)QLEN * D_DIM;          // [3840, 1024]
    float* val = key + (size_t)KVLEN * D_DIM;         // [3840, 1024]

    static cudaStream_t s1 = nullptr;
    static cudaEvent_t eFork = nullptr, eP1 = nullptr, eG1 = nullptr, eTail = nullptr;
    if (!s1) {
        cudaFuncSetAttribute(attn_mma, cudaFuncAttributeMaxDynamicSharedMemorySize, ATT_SMEM);
        cudaFuncSetAttribute(gemm_h<0>, cudaFuncAttributeMaxDynamicSharedMemorySize, GEMM_SMEM);
        cudaFuncSetAttribute(gemm_h<1>, cudaFuncAttributeMaxDynamicSharedMemorySize, GEMM_SMEM);
        cudaFuncSetAttribute(gemm_h<2>, cudaFuncAttributeMaxDynamicSharedMemorySize, GEMM_SMEM);
        cudaStreamCreateWithFlags(&s1, cudaStreamNonBlocking);
        cudaEventCreateWithFlags(&eFork, cudaEventDisableTiming);
        cudaEventCreateWithFlags(&eP1,   cudaEventDisableTiming);
        cudaEventCreateWithFlags(&eG1,   cudaEventDisableTiming);
        cudaEventCreateWithFlags(&eTail, cudaEventDisableTiming);
    }

    unsigned *wq_p, *wkv_p, *wo_p;
    cudaGetSymbolAddress((void**)&wq_p,  g_Wq_h);
    cudaGetSymbolAddress((void**)&wkv_p, g_Wkv_h);
    cudaGetSymbolAddress((void**)&wo_p,  g_Wo_h);

    // ---- fork s1 off the capture (legacy) stream ----
    cudaEventRecord(eFork, 0);
    cudaStreamWaitEvent(s1, eFork, 0);

    // ---- s0 chain: kvin -> Wq -> gemm0 (q proj) ----
    conv_kvin_h<<<512, 256, 0, 0>>>(utter, rctx, mem);
    cudaEventRecord(eP1, 0);                       // kvin ready
    conv_w_h<<<256, 256, 0, 0>>>(Wq, wq_p, D_DIM * D_DIM / 4);
    gemm_h<0><<<dim3(D_DIM / 128, QLEN / 128), 256, GEMM_SMEM, 0>>>(bq, nullptr, nullptr);

    // ---- s1 chain: Wkv -> lc -> (wait kvin) gemm1 -> Wo -> memcpys ----
    conv_w_h<<<512, 256, 0, s1>>>(Wkv, wkv_p, 2 * D_DIM * D_DIM / 4);
    conv_lc<<<256, 256, 0, s1>>>(lck, lcv);
    cudaStreamWaitEvent(s1, eP1, 0);
    gemm_h<1><<<dim3(2 * D_DIM / 128, KVIN / 128), 256, GEMM_SMEM, s1>>>(bkv, key, val);
    cudaEventRecord(eG1, s1);                      // kv + lc ready for attention
    conv_w_h<<<256, 256, 0, s1>>>(Wo, wo_p, D_DIM * D_DIM / 4);
    cudaMemcpyAsync(key + (size_t)MR * D_DIM, lck,
                    (size_t)L_LEN * D_DIM * sizeof(float),
                    cudaMemcpyDeviceToDevice, s1);
    cudaMemcpyAsync(val + (size_t)MR * D_DIM, lcv,
                    (size_t)L_LEN * D_DIM * sizeof(float),
                    cudaMemcpyDeviceToDevice, s1);
    cudaEventRecord(eTail, s1);                    // Wo + d_out splices done

    // ---- s0: attention (overlaps conv_wo + memcpys), then join + gemm2 ----
    cudaStreamWaitEvent(0, eG1, 0);
    attn_mma<<<dim3(NHEAD, QLEN / 128), 256, ATT_SMEM, 0>>>(0);
    cudaStreamWaitEvent(0, eTail, 0);              // join s1 back into capture stream
    gemm_h<2><<<dim3(D_DIM / 128, QLEN / 128), 256, GEMM_SMEM, 0>>>(bo, out, nullptr);
}